// round 13
// baseline (speedup 1.0000x reference)
#include <cuda_runtime.h>
#include <cuda_bf16.h>
#include <stdint.h>

#define C_CH 512
#define HW_  16384
#define NB   8
#define KR   256

typedef __nv_bfloat16 bf16;

// ---------------------------------------------------------------------------
// Static device scratch (allocation-free rule)
// ---------------------------------------------------------------------------
__device__ bf16 g_xh [(size_t)NB * HW_ * C_CH];
__device__ bf16 g_xl [(size_t)NB * HW_ * C_CH];
__device__ bf16 g_t0h[(size_t)NB * HW_ * C_CH];
__device__ bf16 g_t0l[(size_t)NB * HW_ * C_CH];
__device__ bf16 g_qh [(size_t)NB * HW_ * C_CH];
__device__ bf16 g_ql [(size_t)NB * HW_ * C_CH];
__device__ bf16 g_cxh[(size_t)NB * HW_ * C_CH];
__device__ bf16 g_cxl[(size_t)NB * HW_ * C_CH];
__device__ float g_sim[(size_t)NB * HW_ * KR];
__device__ bf16 g_prh[(size_t)NB * HW_ * KR];
__device__ bf16 g_prl[(size_t)NB * HW_ * KR];
__device__ bf16 g_pbh[(size_t)NB * KR * C_CH];
__device__ bf16 g_pbl[(size_t)NB * KR * C_CH];
__device__ bf16 g_kth[(size_t)NB * KR * C_CH];
__device__ bf16 g_ktl[(size_t)NB * KR * C_CH];
__device__ bf16 g_keyh[(size_t)NB * KR * C_CH];
__device__ bf16 g_keyl[(size_t)NB * KR * C_CH];
__device__ bf16 g_vth[(size_t)NB * KR * C_CH];
__device__ bf16 g_vtl[(size_t)NB * KR * C_CH];
__device__ bf16 g_valh[(size_t)NB * C_CH * KR];
__device__ bf16 g_vall[(size_t)NB * C_CH * KR];
__device__ bf16 g_wh[(size_t)7 * C_CH * C_CH];
__device__ bf16 g_wl[(size_t)7 * C_CH * C_CH];

// ---------------------------------------------------------------------------
// mma.sync / ldmatrix / cp.async helpers (legal on target sm_103, no 'a')
// ---------------------------------------------------------------------------
static __device__ __forceinline__ uint32_t smem_u32(const void* p) {
    uint32_t a;
    asm("{ .reg .u64 t; cvta.to.shared.u64 t, %1; cvt.u32.u64 %0, t; }"
        : "=r"(a) : "l"(p));
    return a;
}
static __device__ __forceinline__ void cpa16(uint32_t saddr, const void* g) {
    asm volatile("cp.async.cg.shared.global [%0], [%1], 16;"
                 :: "r"(saddr), "l"(g));
}
static __device__ __forceinline__ void cpa_commit() {
    asm volatile("cp.async.commit_group;" ::: "memory");
}
static __device__ __forceinline__ void cpa_wait0() {
    asm volatile("cp.async.wait_group 0;" ::: "memory");
}
static __device__ __forceinline__ void ldm4(uint32_t* d, uint32_t addr) {
    asm volatile("ldmatrix.sync.aligned.m8n8.x4.shared.b16 {%0,%1,%2,%3}, [%4];"
                 : "=r"(d[0]), "=r"(d[1]), "=r"(d[2]), "=r"(d[3]) : "r"(addr));
}
static __device__ __forceinline__ void mma16816(float* c, const uint32_t* a,
                                                uint32_t b0, uint32_t b1) {
    asm volatile(
        "mma.sync.aligned.m16n8k16.row.col.f32.bf16.bf16.f32 "
        "{%0,%1,%2,%3}, {%4,%5,%6,%7}, {%8,%9}, {%0,%1,%2,%3};"
        : "+f"(c[0]), "+f"(c[1]), "+f"(c[2]), "+f"(c[3])
        : "r"(a[0]), "r"(a[1]), "r"(a[2]), "r"(a[3]), "r"(b0), "r"(b1));
}

// 16B-granular XOR swizzle over rows of 64B (32 bf16): conflict-free for the
// 4-seg row writes and for ldmatrix 8-row gathers.
static __device__ __forceinline__ uint32_t swz(int row, int kb) {
    return (uint32_t)(row * 64 + kb) ^ (uint32_t)((row & 7) << 4);
}

// SMEM: 2 stages x (A_hi 8K | A_lo 8K | B_hi 8K | B_lo 8K) = 64 KiB
#define STAGE_BYTES 32768
#define SMEM_BYTES  (2 * STAGE_BYTES)

// ---------------------------------------------------------------------------
// Tensor-core GEMM:  O[m,n] = sum_k A[m,k]*B[n,k]   (bf16 hi/lo x3, f32 acc)
// EPI: 0 = hi/lo bf16 out, relu, chan=n    1 = hi/lo out, relu, chan=m
//      2 = hi/lo out, no act               3 = f32 out [m][n]
//      4 = f32 out transposed [n][m] via SMEM (coalesced), relu, chan=n
// Block 128x128, BK=32, 256 thr (8 warps of 32x64), cp.async double buffer.
// De-convoy: warp-pair-rotated B order; cp.async issued after kk=0 compute.
// ---------------------------------------------------------------------------
template<int EPI>
__global__ void __launch_bounds__(256, 2) mma_gemm(
    const bf16* __restrict__ Ah, const bf16* __restrict__ Al, int lda, long long sA,
    const bf16* __restrict__ Bh, const bf16* __restrict__ Bl, int ldb, long long sB,
    float* __restrict__ Of, bf16* __restrict__ Ohi, bf16* __restrict__ Olo,
    int ldo, long long sO,
    const float* __restrict__ scale, const float* __restrict__ bias, int Ktot)
{
    extern __shared__ __align__(128) char smem[];
    const uint32_t sb = smem_u32(smem);
    const int tid  = threadIdx.x;
    const int lane = tid & 31, w = tid >> 5;
    const int wm = (w >> 1) * 32, wn = (w & 1) * 64;
    const int n0 = blockIdx.x * 128, m0 = blockIdx.y * 128, z = blockIdx.z;
    const int rot = (w >> 1) & 3;            // B-pair rotation per warp-pair

    const bf16* pAh = Ah + (size_t)z * sA + (size_t)m0 * lda;
    const bf16* pAl = Al + (size_t)z * sA + (size_t)m0 * lda;
    const bf16* pBh = Bh + (size_t)z * sB + (size_t)n0 * ldb;
    const bf16* pBl = Bl + (size_t)z * sB + (size_t)n0 * ldb;

    // ---- async stage loader: 8 x 16B cp.async per thread ----
    auto stage_load = [&](int st, int k0) {
        const uint32_t base = sb + st * STAGE_BYTES;
        #pragma unroll
        for (int it = 0; it < 2; ++it) {
            const int seg = tid + it * 256;          // 0..511
            const int row = seg >> 2;                // 0..127
            const int kb  = (seg & 3) << 4;          // byte offset in row
            const uint32_t so = swz(row, kb);
            const int ke = (kb >> 1);                // elem offset
            const size_t ga = (size_t)row * lda + k0 + ke;
            const size_t gb = (size_t)row * ldb + k0 + ke;
            cpa16(base + 0     + so, pAh + ga);
            cpa16(base + 8192  + so, pAl + ga);
            cpa16(base + 16384 + so, pBh + gb);
            cpa16(base + 24576 + so, pBl + gb);
        }
        cpa_commit();
    };

    float acc[2][8][4];
    #pragma unroll
    for (int mt = 0; mt < 2; ++mt)
        #pragma unroll
        for (int nt = 0; nt < 8; ++nt)
            #pragma unroll
            for (int e = 0; e < 4; ++e) acc[mt][nt][e] = 0.f;

    const int q = lane >> 3, r = lane & 7;   // ldmatrix lane decomposition
    const int nch = Ktot >> 5;

    stage_load(0, 0);
    for (int c = 0; c < nch; ++c) {
        cpa_wait0();
        __syncthreads();

        const uint32_t abase = sb + (c & 1) * STAGE_BYTES;
        const uint32_t bbase = abase + 16384;

        #pragma unroll
        for (int kk = 0; kk < 2; ++kk) {
            // A fragments: 2 m-tiles x (hi, lo)
            uint32_t ah[2][4], al[2][4];
            #pragma unroll
            for (int mt = 0; mt < 2; ++mt) {
                const int arow = wm + mt * 16 + ((q & 1) << 3) + r;
                const int kb   = kk * 32 + ((q >> 1) << 4);
                const uint32_t ad = abase + swz(arow, kb);
                ldm4(ah[mt], ad);
                ldm4(al[mt], ad + 8192);
            }
            // B in pairs of n-tiles, rotated start per warp-pair (de-convoy)
            #pragma unroll
            for (int i = 0; i < 4; ++i) {
                const int np = (i + rot) & 3;
                const int brow = wn + np * 16 + ((q >> 1) << 3) + r;
                const int kb   = kk * 32 + ((q & 1) << 4);
                const uint32_t bd = bbase + swz(brow, kb);
                uint32_t bh[4], bl[4];
                ldm4(bh, bd);
                ldm4(bl, bd + 8192);
                #pragma unroll
                for (int s2 = 0; s2 < 2; ++s2) {
                    const int nt = np * 2 + s2;
                    #pragma unroll
                    for (int mt = 0; mt < 2; ++mt) {
                        mma16816(acc[mt][nt], ah[mt], bh[2 * s2], bh[2 * s2 + 1]);
                        mma16816(acc[mt][nt], ah[mt], bl[2 * s2], bl[2 * s2 + 1]);
                        mma16816(acc[mt][nt], al[mt], bh[2 * s2], bh[2 * s2 + 1]);
                    }
                }
            }
            // issue next chunk's loads after kk=0 compute is queued:
            // first mmas start immediately post-barrier; ~half a chunk of
            // tensor work still remains to hide the cp.async latency.
            if (kk == 0 && c + 1 < nch) stage_load((c + 1) & 1, (c + 1) * 32);
        }
    }

    // ---- epilogue ----
    if constexpr (EPI == 4) {
        // Two-pass transpose through SMEM (reuses stage buffers):
        //   pass p handles n-local rows [p*64, p*64+64). pad=132 floats:
        //   STS.32 writes bank-conflict-free, LDS.128 reads conflict-free
        //   per 8-lane phase, stores fully coalesced (float4 rows).
        float* tb = (float*)smem;
        const int pad = 132;                       // 64*132*4 = 33792 <= 64K
        #pragma unroll
        for (int p = 0; p < 2; ++p) {
            __syncthreads();
            if ((w & 1) == p) {                    // warps owning wn == p*64
                #pragma unroll
                for (int mt = 0; mt < 2; ++mt)
                    #pragma unroll
                    for (int nt = 0; nt < 8; ++nt) {
                        const float* cc = acc[mt][nt];
                        #pragma unroll
                        for (int h = 0; h < 2; ++h) {
                            const int ml = wm + mt * 16 + (lane >> 2) + h * 8;
                            const int nl = nt * 8 + (lane & 3) * 2;   // 0..63
                            const int n  = n0 + p * 64 + nl;
                            float v0 = fmaxf(fmaf(scale[n],     cc[h*2+0], bias[n]),     0.f);
                            float v1 = fmaxf(fmaf(scale[n + 1], cc[h*2+1], bias[n + 1]), 0.f);
                            tb[(size_t)nl * pad + ml]       = v0;
                            tb[(size_t)(nl + 1) * pad + ml] = v1;
                        }
                    }
            }
            __syncthreads();
            // each warp stores 8 rows; 32 lanes cover one 128-float row
            float* ob = Of + (size_t)z * sO + (size_t)(n0 + p * 64) * ldo + m0;
            #pragma unroll
            for (int i = 0; i < 8; ++i) {
                const int nrow = w * 8 + i;
                const float* src = tb + (size_t)nrow * pad + lane * 4;
                float4 v;
                v.x = src[0]; v.y = src[1]; v.z = src[2]; v.w = src[3];
                *(float4*)(ob + (size_t)nrow * ldo + lane * 4) = v;
            }
        }
        return;
    }

    #pragma unroll
    for (int mt = 0; mt < 2; ++mt) {
        #pragma unroll
        for (int nt = 0; nt < 8; ++nt) {
            const float* cc = acc[mt][nt];
            #pragma unroll
            for (int h = 0; h < 2; ++h) {
                const int m = m0 + wm + mt * 16 + (lane >> 2) + h * 8;
                const int n = n0 + wn + nt * 8 + (lane & 3) * 2;
                float v0 = cc[h * 2 + 0];
                float v1 = cc[h * 2 + 1];
                if constexpr (EPI == 0) {
                    v0 = fmaxf(fmaf(scale[n],     v0, bias[n]),     0.f);
                    v1 = fmaxf(fmaf(scale[n + 1], v1, bias[n + 1]), 0.f);
                } else if constexpr (EPI == 1) {
                    const float sm_ = scale[m], bm_ = bias[m];
                    v0 = fmaxf(fmaf(sm_, v0, bm_), 0.f);
                    v1 = fmaxf(fmaf(sm_, v1, bm_), 0.f);
                }
                if constexpr (EPI == 3) {
                    float2 v; v.x = v0; v.y = v1;
                    *(float2*)(Of + (size_t)z * sO + (size_t)m * ldo + n) = v;
                } else {
                    const bf16 h0 = __float2bfloat16(v0);
                    const bf16 h1 = __float2bfloat16(v1);
                    __nv_bfloat162 hh; hh.x = h0; hh.y = h1;
                    __nv_bfloat162 ll;
                    ll.x = __float2bfloat16(v0 - __bfloat162float(h0));
                    ll.y = __float2bfloat16(v1 - __bfloat162float(h1));
                    const size_t off = (size_t)z * sO + (size_t)m * ldo + n;
                    *(__nv_bfloat162*)(Ohi + off) = hh;
                    *(__nv_bfloat162*)(Olo + off) = ll;
                }
            }
        }
    }
}

// ---------------------------------------------------------------------------
// Conversion kernels
// ---------------------------------------------------------------------------
__global__ void split_plain(const float* __restrict__ in, bf16* __restrict__ oh,
                            bf16* __restrict__ ol, int n)
{
    int i = blockIdx.x * 256 + threadIdx.x;
    if (i >= n) return;
    float v = in[i];
    bf16 h = __float2bfloat16(v);
    oh[i] = h;
    ol[i] = __float2bfloat16(v - __bfloat162float(h));
}

// in: [z][Cc][P] f32  ->  out hi/lo: [z][P][Cc] bf16
__global__ void transpose_split(const float* __restrict__ in, bf16* __restrict__ oh,
                                bf16* __restrict__ ol, int P, int Cc)
{
    __shared__ float t[32][33];
    int z = blockIdx.z;
    int p0 = blockIdx.x * 32, c0 = blockIdx.y * 32;
    const float* ib = in + (size_t)z * Cc * P;
    int tx = threadIdx.x, ty = threadIdx.y;
    #pragma unroll
    for (int i = 0; i < 32; i += 8)
        t[ty + i][tx] = ib[(size_t)(c0 + ty + i) * P + p0 + tx];
    __syncthreads();
    bf16* ohb = oh + (size_t)z * P * Cc;
    bf16* olb = ol + (size_t)z * P * Cc;
    #pragma unroll
    for (int i = 0; i < 32; i += 8) {
        float v = t[tx][ty + i];
        bf16 h = __float2bfloat16(v);
        size_t o = (size_t)(p0 + ty + i) * Cc + c0 + tx;
        ohb[o] = h;
        olb[o] = __float2bfloat16(v - __bfloat162float(h));
    }
}

// softmax over K=256 per row; outputs hi/lo bf16 probabilities
__global__ void softmax_split(const float* __restrict__ sim, bf16* __restrict__ ph,
                              bf16* __restrict__ pl, float scale, int nrows)
{
    const int warp = (int)((blockIdx.x * (unsigned)blockDim.x + threadIdx.x) >> 5);
    const int lane = threadIdx.x & 31;
    if (warp >= nrows) return;
    const float* row = sim + (size_t)warp * 256;

    float4 v0 = *(const float4*)(row + lane * 4);
    float4 v1 = *(const float4*)(row + 128 + lane * 4);

    float m = fmaxf(fmaxf(fmaxf(v0.x, v0.y), fmaxf(v0.z, v0.w)),
                    fmaxf(fmaxf(v1.x, v1.y), fmaxf(v1.z, v1.w)));
    #pragma unroll
    for (int o = 16; o; o >>= 1) m = fmaxf(m, __shfl_xor_sync(0xffffffffu, m, o));

    v0.x = __expf((v0.x - m) * scale); v0.y = __expf((v0.y - m) * scale);
    v0.z = __expf((v0.z - m) * scale); v0.w = __expf((v0.w - m) * scale);
    v1.x = __expf((v1.x - m) * scale); v1.y = __expf((v1.y - m) * scale);
    v1.z = __expf((v1.z - m) * scale); v1.w = __expf((v1.w - m) * scale);

    float s = v0.x + v0.y + v0.z + v0.w + v1.x + v1.y + v1.z + v1.w;
    #pragma unroll
    for (int o = 16; o; o >>= 1) s += __shfl_xor_sync(0xffffffffu, s, o);
    const float inv = 1.0f / s;

    float p[8] = {v0.x * inv, v0.y * inv, v0.z * inv, v0.w * inv,
                  v1.x * inv, v1.y * inv, v1.z * inv, v1.w * inv};
    bf16* oh = ph + (size_t)warp * 256;
    bf16* ol = pl + (size_t)warp * 256;
    #pragma unroll
    for (int g = 0; g < 2; g++) {
        int base = (g ? 128 : 0) + lane * 4;
        #pragma unroll
        for (int j = 0; j < 4; j += 2) {
            float a = p[g * 4 + j], b2 = p[g * 4 + j + 1];
            bf16 ha = __float2bfloat16(a), hb = __float2bfloat16(b2);
            __nv_bfloat162 hh; hh.x = ha; hh.y = hb;
            __nv_bfloat162 ll;
            ll.x = __float2bfloat16(a - __bfloat162float(ha));
            ll.y = __float2bfloat16(b2 - __bfloat162float(hb));
            *(__nv_bfloat162*)(oh + base + j) = hh;
            *(__nv_bfloat162*)(ol + base + j) = ll;
        }
    }
}

// ---------------------------------------------------------------------------
// kernel_launch
// Inputs: x [8,512,128,128], proxy [8,512,256,1], W [7,512,512], s [7,512], b [7,512]
// ---------------------------------------------------------------------------
extern "C" void kernel_launch(void* const* d_in, const int* in_sizes, int n_in,
                              void* d_out, int out_size)
{
    (void)in_sizes; (void)n_in; (void)out_size;
    const float* x     = (const float*)d_in[0];
    const float* proxy = (const float*)d_in[1];
    const float* W     = (const float*)d_in[2];
    const float* s     = (const float*)d_in[3];
    const float* b     = (const float*)d_in[4];
    float* out = (float*)d_out;

    bf16 *xh,*xl,*t0h,*t0l,*qh,*ql,*cxh,*cxl,*prh,*prl;
    bf16 *pbh,*pbl,*kth,*ktl,*keyh,*keyl,*vth,*vtl,*valh,*vall,*wh,*wl;
    float *simf;
    cudaGetSymbolAddress((void**)&xh,  g_xh);   cudaGetSymbolAddress((void**)&xl,  g_xl);
    cudaGetSymbolAddress((void**)&t0h, g_t0h);  cudaGetSymbolAddress((void**)&t0l, g_t0l);
    cudaGetSymbolAddress((void**)&qh,  g_qh);   cudaGetSymbolAddress((void**)&ql,  g_ql);
    cudaGetSymbolAddress((void**)&cxh, g_cxh);  cudaGetSymbolAddress((void**)&cxl, g_cxl);
    cudaGetSymbolAddress((void**)&prh, g_prh);  cudaGetSymbolAddress((void**)&prl, g_prl);
    cudaGetSymbolAddress((void**)&pbh, g_pbh);  cudaGetSymbolAddress((void**)&pbl, g_pbl);
    cudaGetSymbolAddress((void**)&kth, g_kth);  cudaGetSymbolAddress((void**)&ktl, g_ktl);
    cudaGetSymbolAddress((void**)&keyh,g_keyh); cudaGetSymbolAddress((void**)&keyl,g_keyl);
    cudaGetSymbolAddress((void**)&vth, g_vth);  cudaGetSymbolAddress((void**)&vtl, g_vtl);
    cudaGetSymbolAddress((void**)&valh,g_valh); cudaGetSymbolAddress((void**)&vall,g_vall);
    cudaGetSymbolAddress((void**)&wh,  g_wh);   cudaGetSymbolAddress((void**)&wl,  g_wl);
    cudaGetSymbolAddress((void**)&simf,g_sim);

    cudaFuncSetAttribute(mma_gemm<0>, cudaFuncAttributeMaxDynamicSharedMemorySize, SMEM_BYTES);
    cudaFuncSetAttribute(mma_gemm<1>, cudaFuncAttributeMaxDynamicSharedMemorySize, SMEM_BYTES);
    cudaFuncSetAttribute(mma_gemm<2>, cudaFuncAttributeMaxDynamicSharedMemorySize, SMEM_BYTES);
    cudaFuncSetAttribute(mma_gemm<3>, cudaFuncAttributeMaxDynamicSharedMemorySize, SMEM_BYTES);
    cudaFuncSetAttribute(mma_gemm<4>, cudaFuncAttributeMaxDynamicSharedMemorySize, SMEM_BYTES);

    const long long sBig = (long long)HW_ * C_CH;     // 8388608
    const long long sP   = (long long)KR  * C_CH;     // 131072
    const long long sSim = (long long)HW_ * KR;       // 4194304
    const long long sW   = (long long)C_CH * C_CH;    // 262144

    // --- conversions ---
    split_plain<<<(int)((7 * sW + 255) / 256), 256>>>(W, wh, wl, (int)(7 * sW));
    transpose_split<<<dim3(HW_ / 32, C_CH / 32, NB), dim3(32, 8)>>>(x, xh, xl, HW_, C_CH);
    transpose_split<<<dim3(KR  / 32, C_CH / 32, NB), dim3(32, 8)>>>(proxy, pbh, pbl, KR, C_CH);

    const dim3 blk(256);
    // f_pixel: x -> t0 -> q   (activations [p][c], chan on N)
    mma_gemm<0><<<dim3(4, 128, NB), blk, SMEM_BYTES>>>(
        xh, xl, C_CH, sBig, wh + 0 * sW, wl + 0 * sW, C_CH, 0,
        nullptr, t0h, t0l, C_CH, sBig, s + 0 * C_CH, b + 0 * C_CH, C_CH);
    mma_gemm<0><<<dim3(4, 128, NB), blk, SMEM_BYTES>>>(
        t0h, t0l, C_CH, sBig, wh + 1 * sW, wl + 1 * sW, C_CH, 0,
        nullptr, qh, ql, C_CH, sBig, s + 1 * C_CH, b + 1 * C_CH, C_CH);

    // f_object: proxy -> kt -> key   ([r][c])
    mma_gemm<0><<<dim3(4, 2, NB), blk, SMEM_BYTES>>>(
        pbh, pbl, C_CH, sP, wh + 2 * sW, wl + 2 * sW, C_CH, 0,
        nullptr, kth, ktl, C_CH, sP, s + 2 * C_CH, b + 2 * C_CH, C_CH);
    mma_gemm<0><<<dim3(4, 2, NB), blk, SMEM_BYTES>>>(
        kth, ktl, C_CH, sP, wh + 3 * sW, wl + 3 * sW, C_CH, 0,
        nullptr, keyh, keyl, C_CH, sP, s + 3 * C_CH, b + 3 * C_CH, C_CH);

    // f_down: proxy -> vt ([r][c]) -> val ([c][r], chan on M)
    mma_gemm<0><<<dim3(4, 2, NB), blk, SMEM_BYTES>>>(
        pbh, pbl, C_CH, sP, wh + 4 * sW, wl + 4 * sW, C_CH, 0,
        nullptr, vth, vtl, C_CH, sP, s + 4 * C_CH, b + 4 * C_CH, C_CH);
    mma_gemm<1><<<dim3(2, 4, NB), blk, SMEM_BYTES>>>(
        wh + 5 * sW, wl + 5 * sW, C_CH, 0, vth, vtl, C_CH, sP,
        nullptr, valh, vall, KR, sP, s + 5 * C_CH, b + 5 * C_CH, C_CH);

    // sim[p,k] = sum_c q[p,c]*key[k,c]  (f32 logits)
    mma_gemm<3><<<dim3(2, 128, NB), blk, SMEM_BYTES>>>(
        qh, ql, C_CH, sBig, keyh, keyl, C_CH, sP,
        simf, nullptr, nullptr, KR, sSim, nullptr, nullptr, C_CH);

    // softmax over k -> probs hi/lo
    softmax_split<<<(NB * HW_) / 8, 256>>>(simf, prh, prl,
                                           0.044194173824159216f, NB * HW_);

    // ctx[p,c] = sum_k probs[p,k]*val[c,k]
    mma_gemm<2><<<dim3(4, 128, NB), blk, SMEM_BYTES>>>(
        prh, prl, KR, sSim, valh, vall, KR, sP,
        nullptr, cxh, cxl, C_CH, sBig, nullptr, nullptr, KR);

    // f_up: out[c,p] = relu(s6*(sum_c' ctx[p,c']*W6[c,c']) + b6), transposed f32 store
    mma_gemm<4><<<dim3(4, 128, NB), blk, SMEM_BYTES>>>(
        cxh, cxl, C_CH, sBig, wh + 6 * sW, wl + 6 * sW, C_CH, 0,
        out, nullptr, nullptr, HW_, (long long)C_CH * HW_,
        s + 6 * C_CH, b + 6 * C_CH, C_CH);
}

// round 14
// speedup vs baseline: 2.4801x; 2.4801x over previous
#include <cuda_runtime.h>
#include <cuda_bf16.h>
#include <stdint.h>

#define C_CH 512
#define HW_  16384
#define NB   8
#define KR   256

typedef __nv_bfloat16 bf16;

// ---------------------------------------------------------------------------
// Static device scratch (allocation-free rule)
// ---------------------------------------------------------------------------
__device__ bf16 g_xh [(size_t)NB * HW_ * C_CH];
__device__ bf16 g_xl [(size_t)NB * HW_ * C_CH];
__device__ bf16 g_t0h[(size_t)NB * HW_ * C_CH];
__device__ bf16 g_t0l[(size_t)NB * HW_ * C_CH];
__device__ bf16 g_qh [(size_t)NB * HW_ * C_CH];
__device__ bf16 g_ql [(size_t)NB * HW_ * C_CH];
__device__ bf16 g_cxh[(size_t)NB * HW_ * C_CH];
__device__ bf16 g_cxl[(size_t)NB * HW_ * C_CH];
__device__ float g_sim[(size_t)NB * HW_ * KR];
__device__ bf16 g_prh[(size_t)NB * HW_ * KR];
__device__ bf16 g_prl[(size_t)NB * HW_ * KR];
__device__ bf16 g_pbh[(size_t)NB * KR * C_CH];
__device__ bf16 g_pbl[(size_t)NB * KR * C_CH];
__device__ bf16 g_kth[(size_t)NB * KR * C_CH];
__device__ bf16 g_ktl[(size_t)NB * KR * C_CH];
__device__ bf16 g_keyh[(size_t)NB * KR * C_CH];
__device__ bf16 g_keyl[(size_t)NB * KR * C_CH];
__device__ bf16 g_vth[(size_t)NB * KR * C_CH];
__device__ bf16 g_vtl[(size_t)NB * KR * C_CH];
__device__ bf16 g_valh[(size_t)NB * C_CH * KR];
__device__ bf16 g_vall[(size_t)NB * C_CH * KR];
__device__ bf16 g_wh[(size_t)7 * C_CH * C_CH];
__device__ bf16 g_wl[(size_t)7 * C_CH * C_CH];

// ---------------------------------------------------------------------------
// mma.sync / ldmatrix / cp.async helpers (legal on target sm_103, no 'a')
// ---------------------------------------------------------------------------
static __device__ __forceinline__ uint32_t smem_u32(const void* p) {
    uint32_t a;
    asm("{ .reg .u64 t; cvta.to.shared.u64 t, %1; cvt.u32.u64 %0, t; }"
        : "=r"(a) : "l"(p));
    return a;
}
static __device__ __forceinline__ void cpa16(uint32_t saddr, const void* g) {
    asm volatile("cp.async.cg.shared.global [%0], [%1], 16;"
                 :: "r"(saddr), "l"(g));
}
static __device__ __forceinline__ void cpa_commit() {
    asm volatile("cp.async.commit_group;" ::: "memory");
}
static __device__ __forceinline__ void cpa_wait0() {
    asm volatile("cp.async.wait_group 0;" ::: "memory");
}
static __device__ __forceinline__ void ldm4(uint32_t* d, uint32_t addr) {
    asm volatile("ldmatrix.sync.aligned.m8n8.x4.shared.b16 {%0,%1,%2,%3}, [%4];"
                 : "=r"(d[0]), "=r"(d[1]), "=r"(d[2]), "=r"(d[3]) : "r"(addr));
}
static __device__ __forceinline__ void mma16816(float* c, const uint32_t* a,
                                                uint32_t b0, uint32_t b1) {
    asm volatile(
        "mma.sync.aligned.m16n8k16.row.col.f32.bf16.bf16.f32 "
        "{%0,%1,%2,%3}, {%4,%5,%6,%7}, {%8,%9}, {%0,%1,%2,%3};"
        : "+f"(c[0]), "+f"(c[1]), "+f"(c[2]), "+f"(c[3])
        : "r"(a[0]), "r"(a[1]), "r"(a[2]), "r"(a[3]), "r"(b0), "r"(b1));
}

// 16B-granular XOR swizzle over rows of 64B (32 bf16): conflict-free for the
// 4-seg row writes and for ldmatrix 8-row gathers.
static __device__ __forceinline__ uint32_t swz(int row, int kb) {
    return (uint32_t)(row * 64 + kb) ^ (uint32_t)((row & 7) << 4);
}

// SMEM: 2 stages x (A_hi 8K | A_lo 8K | B_hi 8K | B_lo 8K) = 64 KiB
#define STAGE_BYTES 32768
#define SMEM_BYTES  (2 * STAGE_BYTES)

// ---------------------------------------------------------------------------
// Tensor-core GEMM:  O[m,n] = sum_k A[m,k]*B[n,k]   (bf16 hi/lo x3, f32 acc)
// EPI: 0 = hi/lo bf16 out, relu, chan=n    1 = hi/lo out, relu, chan=m
//      2 = hi/lo out, no act               3 = f32 out [m][n]
//      4 = f32 out transposed [n][m] via SMEM (coalesced), relu, chan=n
// Block 128x128, BK=32, 256 thr (8 warps of 32x64), cp.async double buffer,
// SINGLE __syncthreads per K-chunk (load for c+1 issued after the barrier).
// ---------------------------------------------------------------------------
template<int EPI>
__global__ void __launch_bounds__(256, 2) mma_gemm(
    const bf16* __restrict__ Ah, const bf16* __restrict__ Al, int lda, long long sA,
    const bf16* __restrict__ Bh, const bf16* __restrict__ Bl, int ldb, long long sB,
    float* __restrict__ Of, bf16* __restrict__ Ohi, bf16* __restrict__ Olo,
    int ldo, long long sO,
    const float* __restrict__ scale, const float* __restrict__ bias, int Ktot)
{
    extern __shared__ __align__(128) char smem[];
    const uint32_t sb = smem_u32(smem);
    const int tid  = threadIdx.x;
    const int lane = tid & 31, w = tid >> 5;
    const int wm = (w >> 1) * 32, wn = (w & 1) * 64;
    const int n0 = blockIdx.x * 128, m0 = blockIdx.y * 128, z = blockIdx.z;

    const bf16* pAh = Ah + (size_t)z * sA + (size_t)m0 * lda;
    const bf16* pAl = Al + (size_t)z * sA + (size_t)m0 * lda;
    const bf16* pBh = Bh + (size_t)z * sB + (size_t)n0 * ldb;
    const bf16* pBl = Bl + (size_t)z * sB + (size_t)n0 * ldb;

    // ---- async stage loader: 8 x 16B cp.async per thread ----
    auto stage_load = [&](int st, int k0) {
        const uint32_t base = sb + st * STAGE_BYTES;
        #pragma unroll
        for (int it = 0; it < 2; ++it) {
            const int seg = tid + it * 256;          // 0..511
            const int row = seg >> 2;                // 0..127
            const int kb  = (seg & 3) << 4;          // byte offset in row
            const uint32_t so = swz(row, kb);
            const int ke = (kb >> 1);                // elem offset
            const size_t ga = (size_t)row * lda + k0 + ke;
            const size_t gb = (size_t)row * ldb + k0 + ke;
            cpa16(base + 0     + so, pAh + ga);
            cpa16(base + 8192  + so, pAl + ga);
            cpa16(base + 16384 + so, pBh + gb);
            cpa16(base + 24576 + so, pBl + gb);
        }
        cpa_commit();
    };

    float acc[2][8][4];
    #pragma unroll
    for (int mt = 0; mt < 2; ++mt)
        #pragma unroll
        for (int nt = 0; nt < 8; ++nt)
            #pragma unroll
            for (int e = 0; e < 4; ++e) acc[mt][nt][e] = 0.f;

    const int q = lane >> 3, r = lane & 7;   // ldmatrix lane decomposition
    const int nch = Ktot >> 5;

    stage_load(0, 0);
    for (int c = 0; c < nch; ++c) {
        // wait for chunk c's data (issued last iteration), then one barrier:
        // all warps are now past compute(c-1), so buffer (c+1)&1 is free.
        cpa_wait0();
        __syncthreads();
        if (c + 1 < nch) stage_load((c + 1) & 1, (c + 1) * 32);

        const uint32_t abase = sb + (c & 1) * STAGE_BYTES;
        const uint32_t bbase = abase + 16384;

        #pragma unroll
        for (int kk = 0; kk < 2; ++kk) {
            // A fragments: 2 m-tiles x (hi, lo)
            uint32_t ah[2][4], al[2][4];
            #pragma unroll
            for (int mt = 0; mt < 2; ++mt) {
                const int arow = wm + mt * 16 + ((q & 1) << 3) + r;
                const int kb   = kk * 32 + ((q >> 1) << 4);
                const uint32_t ad = abase + swz(arow, kb);
                ldm4(ah[mt], ad);
                ldm4(al[mt], ad + 8192);
            }
            // B in pairs of n-tiles (x4 = two n8 tiles)
            #pragma unroll
            for (int np = 0; np < 4; ++np) {
                const int brow = wn + np * 16 + ((q >> 1) << 3) + r;
                const int kb   = kk * 32 + ((q & 1) << 4);
                const uint32_t bd = bbase + swz(brow, kb);
                uint32_t bh[4], bl[4];
                ldm4(bh, bd);
                ldm4(bl, bd + 8192);
                #pragma unroll
                for (int s2 = 0; s2 < 2; ++s2) {
                    const int nt = np * 2 + s2;
                    #pragma unroll
                    for (int mt = 0; mt < 2; ++mt) {
                        mma16816(acc[mt][nt], ah[mt], bh[2 * s2], bh[2 * s2 + 1]);
                        mma16816(acc[mt][nt], ah[mt], bl[2 * s2], bl[2 * s2 + 1]);
                        mma16816(acc[mt][nt], al[mt], bh[2 * s2], bh[2 * s2 + 1]);
                    }
                }
            }
        }
    }

    // ---- epilogue ----
    if constexpr (EPI == 4) {
        // Two-pass transpose through SMEM (reuses stage buffers):
        //   pass p handles n-local rows [p*64, p*64+64). pad=132 floats:
        //   STS.32 writes bank-conflict-free, LDS.128 reads conflict-free
        //   per 8-lane phase, stores fully coalesced (float4 rows).
        float* tb = (float*)smem;
        const int pad = 132;                       // 64*132*4 = 33792 <= 64K
        #pragma unroll
        for (int p = 0; p < 2; ++p) {
            __syncthreads();
            if ((w & 1) == p) {                    // warps owning wn == p*64
                #pragma unroll
                for (int mt = 0; mt < 2; ++mt)
                    #pragma unroll
                    for (int nt = 0; nt < 8; ++nt) {
                        const float* cc = acc[mt][nt];
                        #pragma unroll
                        for (int h = 0; h < 2; ++h) {
                            const int ml = wm + mt * 16 + (lane >> 2) + h * 8;
                            const int nl = nt * 8 + (lane & 3) * 2;   // 0..63
                            const int n  = n0 + p * 64 + nl;
                            float v0 = fmaxf(fmaf(scale[n],     cc[h*2+0], bias[n]),     0.f);
                            float v1 = fmaxf(fmaf(scale[n + 1], cc[h*2+1], bias[n + 1]), 0.f);
                            tb[(size_t)nl * pad + ml]       = v0;
                            tb[(size_t)(nl + 1) * pad + ml] = v1;
                        }
                    }
            }
            __syncthreads();
            // each warp stores 8 rows; 32 lanes cover one 128-float row
            float* ob = Of + (size_t)z * sO + (size_t)(n0 + p * 64) * ldo + m0;
            #pragma unroll
            for (int i = 0; i < 8; ++i) {
                const int nrow = w * 8 + i;
                const float* src = tb + (size_t)nrow * pad + lane * 4;
                float4 v;
                v.x = src[0]; v.y = src[1]; v.z = src[2]; v.w = src[3];
                *(float4*)(ob + (size_t)nrow * ldo + lane * 4) = v;
            }
        }
        return;
    }

    #pragma unroll
    for (int mt = 0; mt < 2; ++mt) {
        #pragma unroll
        for (int nt = 0; nt < 8; ++nt) {
            const float* cc = acc[mt][nt];
            #pragma unroll
            for (int h = 0; h < 2; ++h) {
                const int m = m0 + wm + mt * 16 + (lane >> 2) + h * 8;
                const int n = n0 + wn + nt * 8 + (lane & 3) * 2;
                float v0 = cc[h * 2 + 0];
                float v1 = cc[h * 2 + 1];
                if constexpr (EPI == 0) {
                    v0 = fmaxf(fmaf(scale[n],     v0, bias[n]),     0.f);
                    v1 = fmaxf(fmaf(scale[n + 1], v1, bias[n + 1]), 0.f);
                } else if constexpr (EPI == 1) {
                    const float sm_ = scale[m], bm_ = bias[m];
                    v0 = fmaxf(fmaf(sm_, v0, bm_), 0.f);
                    v1 = fmaxf(fmaf(sm_, v1, bm_), 0.f);
                }
                if constexpr (EPI == 3) {
                    float2 v; v.x = v0; v.y = v1;
                    *(float2*)(Of + (size_t)z * sO + (size_t)m * ldo + n) = v;
                } else {
                    const bf16 h0 = __float2bfloat16(v0);
                    const bf16 h1 = __float2bfloat16(v1);
                    __nv_bfloat162 hh; hh.x = h0; hh.y = h1;
                    __nv_bfloat162 ll;
                    ll.x = __float2bfloat16(v0 - __bfloat162float(h0));
                    ll.y = __float2bfloat16(v1 - __bfloat162float(h1));
                    const size_t off = (size_t)z * sO + (size_t)m * ldo + n;
                    *(__nv_bfloat162*)(Ohi + off) = hh;
                    *(__nv_bfloat162*)(Olo + off) = ll;
                }
            }
        }
    }
}

// ---------------------------------------------------------------------------
// Conversion kernels
// ---------------------------------------------------------------------------
__global__ void split_plain(const float* __restrict__ in, bf16* __restrict__ oh,
                            bf16* __restrict__ ol, int n)
{
    int i = blockIdx.x * 256 + threadIdx.x;
    if (i >= n) return;
    float v = in[i];
    bf16 h = __float2bfloat16(v);
    oh[i] = h;
    ol[i] = __float2bfloat16(v - __bfloat162float(h));
}

// in: [z][Cc][P] f32  ->  out hi/lo: [z][P][Cc] bf16
__global__ void transpose_split(const float* __restrict__ in, bf16* __restrict__ oh,
                                bf16* __restrict__ ol, int P, int Cc)
{
    __shared__ float t[32][33];
    int z = blockIdx.z;
    int p0 = blockIdx.x * 32, c0 = blockIdx.y * 32;
    const float* ib = in + (size_t)z * Cc * P;
    int tx = threadIdx.x, ty = threadIdx.y;
    #pragma unroll
    for (int i = 0; i < 32; i += 8)
        t[ty + i][tx] = ib[(size_t)(c0 + ty + i) * P + p0 + tx];
    __syncthreads();
    bf16* ohb = oh + (size_t)z * P * Cc;
    bf16* olb = ol + (size_t)z * P * Cc;
    #pragma unroll
    for (int i = 0; i < 32; i += 8) {
        float v = t[tx][ty + i];
        bf16 h = __float2bfloat16(v);
        size_t o = (size_t)(p0 + ty + i) * Cc + c0 + tx;
        ohb[o] = h;
        olb[o] = __float2bfloat16(v - __bfloat162float(h));
    }
}

// softmax over K=256 per row; outputs hi/lo bf16 probabilities
__global__ void softmax_split(const float* __restrict__ sim, bf16* __restrict__ ph,
                              bf16* __restrict__ pl, float scale, int nrows)
{
    const int warp = (int)((blockIdx.x * (unsigned)blockDim.x + threadIdx.x) >> 5);
    const int lane = threadIdx.x & 31;
    if (warp >= nrows) return;
    const float* row = sim + (size_t)warp * 256;

    float4 v0 = *(const float4*)(row + lane * 4);
    float4 v1 = *(const float4*)(row + 128 + lane * 4);

    float m = fmaxf(fmaxf(fmaxf(v0.x, v0.y), fmaxf(v0.z, v0.w)),
                    fmaxf(fmaxf(v1.x, v1.y), fmaxf(v1.z, v1.w)));
    #pragma unroll
    for (int o = 16; o; o >>= 1) m = fmaxf(m, __shfl_xor_sync(0xffffffffu, m, o));

    v0.x = __expf((v0.x - m) * scale); v0.y = __expf((v0.y - m) * scale);
    v0.z = __expf((v0.z - m) * scale); v0.w = __expf((v0.w - m) * scale);
    v1.x = __expf((v1.x - m) * scale); v1.y = __expf((v1.y - m) * scale);
    v1.z = __expf((v1.z - m) * scale); v1.w = __expf((v1.w - m) * scale);

    float s = v0.x + v0.y + v0.z + v0.w + v1.x + v1.y + v1.z + v1.w;
    #pragma unroll
    for (int o = 16; o; o >>= 1) s += __shfl_xor_sync(0xffffffffu, s, o);
    const float inv = 1.0f / s;

    float p[8] = {v0.x * inv, v0.y * inv, v0.z * inv, v0.w * inv,
                  v1.x * inv, v1.y * inv, v1.z * inv, v1.w * inv};
    bf16* oh = ph + (size_t)warp * 256;
    bf16* ol = pl + (size_t)warp * 256;
    #pragma unroll
    for (int g = 0; g < 2; g++) {
        int base = (g ? 128 : 0) + lane * 4;
        #pragma unroll
        for (int j = 0; j < 4; j += 2) {
            float a = p[g * 4 + j], b2 = p[g * 4 + j + 1];
            bf16 ha = __float2bfloat16(a), hb = __float2bfloat16(b2);
            __nv_bfloat162 hh; hh.x = ha; hh.y = hb;
            __nv_bfloat162 ll;
            ll.x = __float2bfloat16(a - __bfloat162float(ha));
            ll.y = __float2bfloat16(b2 - __bfloat162float(hb));
            *(__nv_bfloat162*)(oh + base + j) = hh;
            *(__nv_bfloat162*)(ol + base + j) = ll;
        }
    }
}

// ---------------------------------------------------------------------------
// kernel_launch
// Inputs: x [8,512,128,128], proxy [8,512,256,1], W [7,512,512], s [7,512], b [7,512]
// ---------------------------------------------------------------------------
extern "C" void kernel_launch(void* const* d_in, const int* in_sizes, int n_in,
                              void* d_out, int out_size)
{
    (void)in_sizes; (void)n_in; (void)out_size;
    const float* x     = (const float*)d_in[0];
    const float* proxy = (const float*)d_in[1];
    const float* W     = (const float*)d_in[2];
    const float* s     = (const float*)d_in[3];
    const float* b     = (const float*)d_in[4];
    float* out = (float*)d_out;

    bf16 *xh,*xl,*t0h,*t0l,*qh,*ql,*cxh,*cxl,*prh,*prl;
    bf16 *pbh,*pbl,*kth,*ktl,*keyh,*keyl,*vth,*vtl,*valh,*vall,*wh,*wl;
    float *simf;
    cudaGetSymbolAddress((void**)&xh,  g_xh);   cudaGetSymbolAddress((void**)&xl,  g_xl);
    cudaGetSymbolAddress((void**)&t0h, g_t0h);  cudaGetSymbolAddress((void**)&t0l, g_t0l);
    cudaGetSymbolAddress((void**)&qh,  g_qh);   cudaGetSymbolAddress((void**)&ql,  g_ql);
    cudaGetSymbolAddress((void**)&cxh, g_cxh);  cudaGetSymbolAddress((void**)&cxl, g_cxl);
    cudaGetSymbolAddress((void**)&prh, g_prh);  cudaGetSymbolAddress((void**)&prl, g_prl);
    cudaGetSymbolAddress((void**)&pbh, g_pbh);  cudaGetSymbolAddress((void**)&pbl, g_pbl);
    cudaGetSymbolAddress((void**)&kth, g_kth);  cudaGetSymbolAddress((void**)&ktl, g_ktl);
    cudaGetSymbolAddress((void**)&keyh,g_keyh); cudaGetSymbolAddress((void**)&keyl,g_keyl);
    cudaGetSymbolAddress((void**)&vth, g_vth);  cudaGetSymbolAddress((void**)&vtl, g_vtl);
    cudaGetSymbolAddress((void**)&valh,g_valh); cudaGetSymbolAddress((void**)&vall,g_vall);
    cudaGetSymbolAddress((void**)&wh,  g_wh);   cudaGetSymbolAddress((void**)&wl,  g_wl);
    cudaGetSymbolAddress((void**)&simf,g_sim);

    cudaFuncSetAttribute(mma_gemm<0>, cudaFuncAttributeMaxDynamicSharedMemorySize, SMEM_BYTES);
    cudaFuncSetAttribute(mma_gemm<1>, cudaFuncAttributeMaxDynamicSharedMemorySize, SMEM_BYTES);
    cudaFuncSetAttribute(mma_gemm<2>, cudaFuncAttributeMaxDynamicSharedMemorySize, SMEM_BYTES);
    cudaFuncSetAttribute(mma_gemm<3>, cudaFuncAttributeMaxDynamicSharedMemorySize, SMEM_BYTES);
    cudaFuncSetAttribute(mma_gemm<4>, cudaFuncAttributeMaxDynamicSharedMemorySize, SMEM_BYTES);

    const long long sBig = (long long)HW_ * C_CH;     // 8388608
    const long long sP   = (long long)KR  * C_CH;     // 131072
    const long long sSim = (long long)HW_ * KR;       // 4194304
    const long long sW   = (long long)C_CH * C_CH;    // 262144

    // --- conversions ---
    split_plain<<<(int)((7 * sW + 255) / 256), 256>>>(W, wh, wl, (int)(7 * sW));
    transpose_split<<<dim3(HW_ / 32, C_CH / 32, NB), dim3(32, 8)>>>(x, xh, xl, HW_, C_CH);
    transpose_split<<<dim3(KR  / 32, C_CH / 32, NB), dim3(32, 8)>>>(proxy, pbh, pbl, KR, C_CH);

    const dim3 blk(256);
    // f_pixel: x -> t0 -> q   (activations [p][c], chan on N)
    mma_gemm<0><<<dim3(4, 128, NB), blk, SMEM_BYTES>>>(
        xh, xl, C_CH, sBig, wh + 0 * sW, wl + 0 * sW, C_CH, 0,
        nullptr, t0h, t0l, C_CH, sBig, s + 0 * C_CH, b + 0 * C_CH, C_CH);
    mma_gemm<0><<<dim3(4, 128, NB), blk, SMEM_BYTES>>>(
        t0h, t0l, C_CH, sBig, wh + 1 * sW, wl + 1 * sW, C_CH, 0,
        nullptr, qh, ql, C_CH, sBig, s + 1 * C_CH, b + 1 * C_CH, C_CH);

    // f_object: proxy -> kt -> key   ([r][c])
    mma_gemm<0><<<dim3(4, 2, NB), blk, SMEM_BYTES>>>(
        pbh, pbl, C_CH, sP, wh + 2 * sW, wl + 2 * sW, C_CH, 0,
        nullptr, kth, ktl, C_CH, sP, s + 2 * C_CH, b + 2 * C_CH, C_CH);
    mma_gemm<0><<<dim3(4, 2, NB), blk, SMEM_BYTES>>>(
        kth, ktl, C_CH, sP, wh + 3 * sW, wl + 3 * sW, C_CH, 0,
        nullptr, keyh, keyl, C_CH, sP, s + 3 * C_CH, b + 3 * C_CH, C_CH);

    // f_down: proxy -> vt ([r][c]) -> val ([c][r], chan on M)
    mma_gemm<0><<<dim3(4, 2, NB), blk, SMEM_BYTES>>>(
        pbh, pbl, C_CH, sP, wh + 4 * sW, wl + 4 * sW, C_CH, 0,
        nullptr, vth, vtl, C_CH, sP, s + 4 * C_CH, b + 4 * C_CH, C_CH);
    mma_gemm<1><<<dim3(2, 4, NB), blk, SMEM_BYTES>>>(
        wh + 5 * sW, wl + 5 * sW, C_CH, 0, vth, vtl, C_CH, sP,
        nullptr, valh, vall, KR, sP, s + 5 * C_CH, b + 5 * C_CH, C_CH);

    // sim[p,k] = sum_c q[p,c]*key[k,c]  (f32 logits)
    mma_gemm<3><<<dim3(2, 128, NB), blk, SMEM_BYTES>>>(
        qh, ql, C_CH, sBig, keyh, keyl, C_CH, sP,
        simf, nullptr, nullptr, KR, sSim, nullptr, nullptr, C_CH);

    // softmax over k -> probs hi/lo
    softmax_split<<<(NB * HW_) / 8, 256>>>(simf, prh, prl,
                                           0.044194173824159216f, NB * HW_);

    // ctx[p,c] = sum_k probs[p,k]*val[c,k]
    mma_gemm<2><<<dim3(4, 128, NB), blk, SMEM_BYTES>>>(
        prh, prl, KR, sSim, valh, vall, KR, sP,
        nullptr, cxh, cxl, C_CH, sBig, nullptr, nullptr, KR);

    // f_up: out[c,p] = relu(s6*(sum_c' ctx[p,c']*W6[c,c']) + b6), transposed f32 store
    mma_gemm<4><<<dim3(4, 128, NB), blk, SMEM_BYTES>>>(
        cxh, cxl, C_CH, sBig, wh + 6 * sW, wl + 6 * sW, C_CH, 0,
        out, nullptr, nullptr, HW_, (long long)C_CH * HW_,
        s + 6 * C_CH, b + 6 * C_CH, C_CH);
}

// round 16
// speedup vs baseline: 3.7692x; 1.5198x over previous
#include <cuda_runtime.h>
#include <cuda_fp16.h>
#include <stdint.h>

#define C_CH 512
#define HW_  16384
#define NB   8
#define KR   256

typedef __half f16;

// ---------------------------------------------------------------------------
// Static device scratch (allocation-free rule)
// Activations are single-fp16 (A-side operands); B-side operands (weights,
// key, val, vt) keep hi/lo fp16 splits.
// ---------------------------------------------------------------------------
__device__ f16 g_x  [(size_t)NB * HW_ * C_CH];
__device__ f16 g_t0 [(size_t)NB * HW_ * C_CH];
__device__ f16 g_q  [(size_t)NB * HW_ * C_CH];
__device__ f16 g_cx [(size_t)NB * HW_ * C_CH];
__device__ float g_sim[(size_t)NB * HW_ * KR];
__device__ f16 g_pr [(size_t)NB * HW_ * KR];
__device__ f16 g_pb [(size_t)NB * KR * C_CH];
__device__ f16 g_kt [(size_t)NB * KR * C_CH];
__device__ f16 g_keyh[(size_t)NB * KR * C_CH];
__device__ f16 g_keyl[(size_t)NB * KR * C_CH];
__device__ f16 g_vth[(size_t)NB * KR * C_CH];
__device__ f16 g_vtl[(size_t)NB * KR * C_CH];
__device__ f16 g_valh[(size_t)NB * C_CH * KR];
__device__ f16 g_vall[(size_t)NB * C_CH * KR];
__device__ f16 g_wh[(size_t)7 * C_CH * C_CH];
__device__ f16 g_wl[(size_t)7 * C_CH * C_CH];

// ---------------------------------------------------------------------------
// mma.sync / ldmatrix / cp.async helpers (legal on target sm_103, no 'a')
// ---------------------------------------------------------------------------
static __device__ __forceinline__ uint32_t smem_u32(const void* p) {
    uint32_t a;
    asm("{ .reg .u64 t; cvta.to.shared.u64 t, %1; cvt.u32.u64 %0, t; }"
        : "=r"(a) : "l"(p));
    return a;
}
static __device__ __forceinline__ void cpa16(uint32_t saddr, const void* g) {
    asm volatile("cp.async.cg.shared.global [%0], [%1], 16;"
                 :: "r"(saddr), "l"(g));
}
static __device__ __forceinline__ void cpa_commit() {
    asm volatile("cp.async.commit_group;" ::: "memory");
}
static __device__ __forceinline__ void cpa_wait0() {
    asm volatile("cp.async.wait_group 0;" ::: "memory");
}
static __device__ __forceinline__ void ldm4(uint32_t* d, uint32_t addr) {
    asm volatile("ldmatrix.sync.aligned.m8n8.x4.shared.b16 {%0,%1,%2,%3}, [%4];"
                 : "=r"(d[0]), "=r"(d[1]), "=r"(d[2]), "=r"(d[3]) : "r"(addr));
}
static __device__ __forceinline__ void mma16816(float* c, const uint32_t* a,
                                                uint32_t b0, uint32_t b1) {
    asm volatile(
        "mma.sync.aligned.m16n8k16.row.col.f32.f16.f16.f32 "
        "{%0,%1,%2,%3}, {%4,%5,%6,%7}, {%8,%9}, {%0,%1,%2,%3};"
        : "+f"(c[0]), "+f"(c[1]), "+f"(c[2]), "+f"(c[3])
        : "r"(a[0]), "r"(a[1]), "r"(a[2]), "r"(a[3]), "r"(b0), "r"(b1));
}

// 16B-granular XOR swizzle over rows of 64B (32 f16): conflict-free for the
// 4-seg row writes and for ldmatrix 8-row gathers.
static __device__ __forceinline__ uint32_t swz(int row, int kb) {
    return (uint32_t)(row * 64 + kb) ^ (uint32_t)((row & 7) << 4);
}

// SMEM: 2 stages x (A 8K | B_hi 8K | B_lo 8K) = 48 KiB
#define STAGE_BYTES 24576
#define SMEM_BYTES  (2 * STAGE_BYTES)

// ---------------------------------------------------------------------------
// Tensor-core GEMM:  O[m,n] = sum_k A[m,k]*B[n,k]
//   A single fp16; B fp16 hi/lo (2 mma terms: A*Bh + A*Bl), fp32 accum.
// EPI: 0 = hi-only out, relu, chan=n      1 = hi/lo out, relu, chan=n
//      2 = hi/lo out, relu, chan=m        3 = hi-only out, no act
//      4 = f32 out [m][n]                 5 = f32 out transposed, relu, chan=n
// Block 128x128, BK=32, 256 thr (8 warps of 32x64), cp.async double buffer,
// single __syncthreads per K-chunk (R9-proven skeleton).
// ---------------------------------------------------------------------------
template<int EPI>
__global__ void __launch_bounds__(256, 2) mma_gemm(
    const f16* __restrict__ A, int lda, long long sA,
    const f16* __restrict__ Bh, const f16* __restrict__ Bl, int ldb, long long sB,
    float* __restrict__ Of, f16* __restrict__ Ohi, f16* __restrict__ Olo,
    int ldo, long long sO,
    const float* __restrict__ scale, const float* __restrict__ bias, int Ktot)
{
    extern __shared__ __align__(128) char smem[];
    const uint32_t sb = smem_u32(smem);
    const int tid  = threadIdx.x;
    const int lane = tid & 31, w = tid >> 5;
    const int wm = (w >> 1) * 32, wn = (w & 1) * 64;
    const int n0 = blockIdx.x * 128, m0 = blockIdx.y * 128, z = blockIdx.z;

    const f16* pA  = A  + (size_t)z * sA + (size_t)m0 * lda;
    const f16* pBh = Bh + (size_t)z * sB + (size_t)n0 * ldb;
    const f16* pBl = Bl + (size_t)z * sB + (size_t)n0 * ldb;

    // ---- async stage loader: 6 x 16B cp.async per thread ----
    auto stage_load = [&](int st, int k0) {
        const uint32_t base = sb + st * STAGE_BYTES;
        #pragma unroll
        for (int it = 0; it < 2; ++it) {
            const int seg = tid + it * 256;          // 0..511
            const int row = seg >> 2;                // 0..127
            const int kb  = (seg & 3) << 4;          // byte offset in row
            const uint32_t so = swz(row, kb);
            const int ke = (kb >> 1);                // f16 elem offset
            const size_t ga = (size_t)row * lda + k0 + ke;
            const size_t gb = (size_t)row * ldb + k0 + ke;
            cpa16(base + 0     + so, pA  + ga);
            cpa16(base + 8192  + so, pBh + gb);
            cpa16(base + 16384 + so, pBl + gb);
        }
        cpa_commit();
    };

    float acc[2][8][4];
    #pragma unroll
    for (int mt = 0; mt < 2; ++mt)
        #pragma unroll
        for (int nt = 0; nt < 8; ++nt)
            #pragma unroll
            for (int e = 0; e < 4; ++e) acc[mt][nt][e] = 0.f;

    const int q = lane >> 3, r = lane & 7;   // ldmatrix lane decomposition
    const int nch = Ktot >> 5;

    stage_load(0, 0);
    for (int c = 0; c < nch; ++c) {
        cpa_wait0();
        __syncthreads();
        if (c + 1 < nch) stage_load((c + 1) & 1, (c + 1) * 32);

        const uint32_t abase = sb + (c & 1) * STAGE_BYTES;
        const uint32_t bbase = abase + 8192;

        #pragma unroll
        for (int kk = 0; kk < 2; ++kk) {
            // A fragments: 2 m-tiles
            uint32_t ah[2][4];
            #pragma unroll
            for (int mt = 0; mt < 2; ++mt) {
                const int arow = wm + mt * 16 + ((q & 1) << 3) + r;
                const int kb   = kk * 32 + ((q >> 1) << 4);
                ldm4(ah[mt], abase + swz(arow, kb));
            }
            // B in pairs of n-tiles (x4 = two n8 tiles), hi + lo panels
            #pragma unroll
            for (int np = 0; np < 4; ++np) {
                const int brow = wn + np * 16 + ((q >> 1) << 3) + r;
                const int kb   = kk * 32 + ((q & 1) << 4);
                const uint32_t bd = bbase + swz(brow, kb);
                uint32_t bh[4], bl[4];
                ldm4(bh, bd);
                ldm4(bl, bd + 8192);
                #pragma unroll
                for (int s2 = 0; s2 < 2; ++s2) {
                    const int nt = np * 2 + s2;
                    #pragma unroll
                    for (int mt = 0; mt < 2; ++mt) {
                        mma16816(acc[mt][nt], ah[mt], bh[2 * s2], bh[2 * s2 + 1]);
                        mma16816(acc[mt][nt], ah[mt], bl[2 * s2], bl[2 * s2 + 1]);
                    }
                }
            }
        }
    }

    // ---- epilogue ----
    if constexpr (EPI == 5) {
        // Two-pass transpose through SMEM, coalesced f32 stores (proven EPI4).
        float* tb = (float*)smem;
        const int pad = 132;                       // 64*132*4 = 33792 <= 48K
        #pragma unroll
        for (int p = 0; p < 2; ++p) {
            __syncthreads();
            if ((w & 1) == p) {
                #pragma unroll
                for (int mt = 0; mt < 2; ++mt)
                    #pragma unroll
                    for (int nt = 0; nt < 8; ++nt) {
                        const float* cc = acc[mt][nt];
                        #pragma unroll
                        for (int h = 0; h < 2; ++h) {
                            const int ml = wm + mt * 16 + (lane >> 2) + h * 8;
                            const int nl = nt * 8 + (lane & 3) * 2;
                            const int n  = n0 + p * 64 + nl;
                            float v0 = fmaxf(fmaf(scale[n],     cc[h*2+0], bias[n]),     0.f);
                            float v1 = fmaxf(fmaf(scale[n + 1], cc[h*2+1], bias[n + 1]), 0.f);
                            tb[(size_t)nl * pad + ml]       = v0;
                            tb[(size_t)(nl + 1) * pad + ml] = v1;
                        }
                    }
            }
            __syncthreads();
            float* ob = Of + (size_t)z * sO + (size_t)(n0 + p * 64) * ldo + m0;
            #pragma unroll
            for (int i = 0; i < 8; ++i) {
                const int nrow = w * 8 + i;
                const float* src = tb + (size_t)nrow * pad + lane * 4;
                float4 v;
                v.x = src[0]; v.y = src[1]; v.z = src[2]; v.w = src[3];
                *(float4*)(ob + (size_t)nrow * ldo + lane * 4) = v;
            }
        }
        return;
    }

    #pragma unroll
    for (int mt = 0; mt < 2; ++mt) {
        #pragma unroll
        for (int nt = 0; nt < 8; ++nt) {
            const float* cc = acc[mt][nt];
            #pragma unroll
            for (int h = 0; h < 2; ++h) {
                const int m = m0 + wm + mt * 16 + (lane >> 2) + h * 8;
                const int n = n0 + wn + nt * 8 + (lane & 3) * 2;
                float v0 = cc[h * 2 + 0];
                float v1 = cc[h * 2 + 1];
                if constexpr (EPI == 0 || EPI == 1) {
                    v0 = fmaxf(fmaf(scale[n],     v0, bias[n]),     0.f);
                    v1 = fmaxf(fmaf(scale[n + 1], v1, bias[n + 1]), 0.f);
                } else if constexpr (EPI == 2) {
                    const float sm_ = scale[m], bm_ = bias[m];
                    v0 = fmaxf(fmaf(sm_, v0, bm_), 0.f);
                    v1 = fmaxf(fmaf(sm_, v1, bm_), 0.f);
                }
                if constexpr (EPI == 4) {
                    float2 v; v.x = v0; v.y = v1;
                    *(float2*)(Of + (size_t)z * sO + (size_t)m * ldo + n) = v;
                } else {
                    const size_t off = (size_t)z * sO + (size_t)m * ldo + n;
                    const f16 h0 = __float2half(v0);
                    const f16 h1 = __float2half(v1);
                    __half2 hh; hh.x = h0; hh.y = h1;
                    *(__half2*)(Ohi + off) = hh;
                    if constexpr (EPI == 1 || EPI == 2) {
                        __half2 ll;
                        ll.x = __float2half(v0 - __half2float(h0));
                        ll.y = __float2half(v1 - __half2float(h1));
                        *(__half2*)(Olo + off) = ll;
                    }
                }
            }
        }
    }
}

// ---------------------------------------------------------------------------
// Conversion kernels
// ---------------------------------------------------------------------------
// weights: fp16 hi/lo split
__global__ void split_w(const float* __restrict__ in, f16* __restrict__ oh,
                        f16* __restrict__ ol, int n)
{
    int i = blockIdx.x * 256 + threadIdx.x;
    if (i >= n) return;
    float v = in[i];
    f16 h = __float2half(v);
    oh[i] = h;
    ol[i] = __float2half(v - __half2float(h));
}

// in: [z][Cc][P] f32  ->  out: [z][P][Cc] fp16 (hi only)
__global__ void transpose_half(const float* __restrict__ in, f16* __restrict__ oh,
                               int P, int Cc)
{
    __shared__ float t[32][33];
    int z = blockIdx.z;
    int p0 = blockIdx.x * 32, c0 = blockIdx.y * 32;
    const float* ib = in + (size_t)z * Cc * P;
    int tx = threadIdx.x, ty = threadIdx.y;
    #pragma unroll
    for (int i = 0; i < 32; i += 8)
        t[ty + i][tx] = ib[(size_t)(c0 + ty + i) * P + p0 + tx];
    __syncthreads();
    f16* ohb = oh + (size_t)z * P * Cc;
    #pragma unroll
    for (int i = 0; i < 32; i += 8)
        ohb[(size_t)(p0 + ty + i) * Cc + c0 + tx] = __float2half(t[tx][ty + i]);
}

// softmax over K=256 per row; outputs fp16 probabilities
__global__ void softmax_h(const float* __restrict__ sim, f16* __restrict__ pr,
                          float scale, int nrows)
{
    const int warp = (int)((blockIdx.x * (unsigned)blockDim.x + threadIdx.x) >> 5);
    const int lane = threadIdx.x & 31;
    if (warp >= nrows) return;
    const float* row = sim + (size_t)warp * 256;

    float4 v0 = *(const float4*)(row + lane * 4);
    float4 v1 = *(const float4*)(row + 128 + lane * 4);

    float m = fmaxf(fmaxf(fmaxf(v0.x, v0.y), fmaxf(v0.z, v0.w)),
                    fmaxf(fmaxf(v1.x, v1.y), fmaxf(v1.z, v1.w)));
    #pragma unroll
    for (int o = 16; o; o >>= 1) m = fmaxf(m, __shfl_xor_sync(0xffffffffu, m, o));

    v0.x = __expf((v0.x - m) * scale); v0.y = __expf((v0.y - m) * scale);
    v0.z = __expf((v0.z - m) * scale); v0.w = __expf((v0.w - m) * scale);
    v1.x = __expf((v1.x - m) * scale); v1.y = __expf((v1.y - m) * scale);
    v1.z = __expf((v1.z - m) * scale); v1.w = __expf((v1.w - m) * scale);

    float s = v0.x + v0.y + v0.z + v0.w + v1.x + v1.y + v1.z + v1.w;
    #pragma unroll
    for (int o = 16; o; o >>= 1) s += __shfl_xor_sync(0xffffffffu, s, o);
    const float inv = 1.0f / s;

    f16* op = pr + (size_t)warp * 256;
    __half2 a0; a0.x = __float2half(v0.x * inv); a0.y = __float2half(v0.y * inv);
    __half2 a1; a1.x = __float2half(v0.z * inv); a1.y = __float2half(v0.w * inv);
    __half2 a2; a2.x = __float2half(v1.x * inv); a2.y = __float2half(v1.y * inv);
    __half2 a3; a3.x = __float2half(v1.z * inv); a3.y = __float2half(v1.w * inv);
    *(__half2*)(op + lane * 4)           = a0;
    *(__half2*)(op + lane * 4 + 2)       = a1;
    *(__half2*)(op + 128 + lane * 4)     = a2;
    *(__half2*)(op + 128 + lane * 4 + 2) = a3;
}

// ---------------------------------------------------------------------------
// kernel_launch
// Inputs: x [8,512,128,128], proxy [8,512,256,1], W [7,512,512], s [7,512], b [7,512]
// ---------------------------------------------------------------------------
extern "C" void kernel_launch(void* const* d_in, const int* in_sizes, int n_in,
                              void* d_out, int out_size)
{
    (void)in_sizes; (void)n_in; (void)out_size;
    const float* x     = (const float*)d_in[0];
    const float* proxy = (const float*)d_in[1];
    const float* W     = (const float*)d_in[2];
    const float* s     = (const float*)d_in[3];
    const float* b     = (const float*)d_in[4];
    float* out = (float*)d_out;

    f16 *xb,*t0,*qb,*cx,*pr,*pb,*kt,*keyh,*keyl,*vth,*vtl,*valh,*vall,*wh,*wl;
    float *simf;
    cudaGetSymbolAddress((void**)&xb,  g_x);    cudaGetSymbolAddress((void**)&t0,  g_t0);
    cudaGetSymbolAddress((void**)&qb,  g_q);    cudaGetSymbolAddress((void**)&cx,  g_cx);
    cudaGetSymbolAddress((void**)&pr,  g_pr);   cudaGetSymbolAddress((void**)&pb,  g_pb);
    cudaGetSymbolAddress((void**)&kt,  g_kt);
    cudaGetSymbolAddress((void**)&keyh,g_keyh); cudaGetSymbolAddress((void**)&keyl,g_keyl);
    cudaGetSymbolAddress((void**)&vth, g_vth);  cudaGetSymbolAddress((void**)&vtl, g_vtl);
    cudaGetSymbolAddress((void**)&valh,g_valh); cudaGetSymbolAddress((void**)&vall,g_vall);
    cudaGetSymbolAddress((void**)&wh,  g_wh);   cudaGetSymbolAddress((void**)&wl,  g_wl);
    cudaGetSymbolAddress((void**)&simf,g_sim);

    cudaFuncSetAttribute(mma_gemm<0>, cudaFuncAttributeMaxDynamicSharedMemorySize, SMEM_BYTES);
    cudaFuncSetAttribute(mma_gemm<1>, cudaFuncAttributeMaxDynamicSharedMemorySize, SMEM_BYTES);
    cudaFuncSetAttribute(mma_gemm<2>, cudaFuncAttributeMaxDynamicSharedMemorySize, SMEM_BYTES);
    cudaFuncSetAttribute(mma_gemm<3>, cudaFuncAttributeMaxDynamicSharedMemorySize, SMEM_BYTES);
    cudaFuncSetAttribute(mma_gemm<4>, cudaFuncAttributeMaxDynamicSharedMemorySize, SMEM_BYTES);
    cudaFuncSetAttribute(mma_gemm<5>, cudaFuncAttributeMaxDynamicSharedMemorySize, SMEM_BYTES);

    const long long sBig = (long long)HW_ * C_CH;     // 8388608
    const long long sP   = (long long)KR  * C_CH;     // 131072
    const long long sSim = (long long)HW_ * KR;       // 4194304
    const long long sW   = (long long)C_CH * C_CH;    // 262144

    // --- conversions ---
    split_w<<<(int)((7 * sW + 255) / 256), 256>>>(W, wh, wl, (int)(7 * sW));
    transpose_half<<<dim3(HW_ / 32, C_CH / 32, NB), dim3(32, 8)>>>(x, xb, HW_, C_CH);
    transpose_half<<<dim3(KR  / 32, C_CH / 32, NB), dim3(32, 8)>>>(proxy, pb, KR, C_CH);

    const dim3 blk(256);
    // f_pixel: x -> t0 -> q   (activations [p][c], chan on N; hi-only out)
    mma_gemm<0><<<dim3(4, 128, NB), blk, SMEM_BYTES>>>(
        xb, C_CH, sBig, wh + 0 * sW, wl + 0 * sW, C_CH, 0,
        nullptr, t0, nullptr, C_CH, sBig, s + 0 * C_CH, b + 0 * C_CH, C_CH);
    mma_gemm<0><<<dim3(4, 128, NB), blk, SMEM_BYTES>>>(
        t0, C_CH, sBig, wh + 1 * sW, wl + 1 * sW, C_CH, 0,
        nullptr, qb, nullptr, C_CH, sBig, s + 1 * C_CH, b + 1 * C_CH, C_CH);

    // f_object: proxy -> kt (hi-only) -> key (hi/lo: consumed as B in sim)
    mma_gemm<0><<<dim3(4, 2, NB), blk, SMEM_BYTES>>>(
        pb, C_CH, sP, wh + 2 * sW, wl + 2 * sW, C_CH, 0,
        nullptr, kt, nullptr, C_CH, sP, s + 2 * C_CH, b + 2 * C_CH, C_CH);
    mma_gemm<1><<<dim3(4, 2, NB), blk, SMEM_BYTES>>>(
        kt, C_CH, sP, wh + 3 * sW, wl + 3 * sW, C_CH, 0,
        nullptr, keyh, keyl, C_CH, sP, s + 3 * C_CH, b + 3 * C_CH, C_CH);

    // f_down: proxy -> vt (hi/lo: B of val-gemm) -> val (hi/lo: B of ctx)
    mma_gemm<1><<<dim3(4, 2, NB), blk, SMEM_BYTES>>>(
        pb, C_CH, sP, wh + 4 * sW, wl + 4 * sW, C_CH, 0,
        nullptr, vth, vtl, C_CH, sP, s + 4 * C_CH, b + 4 * C_CH, C_CH);
    // val[c][r] = relu(s5[c]*sum_c' W5[c,c']*vt[r,c'] + b5[c]): A=W5 (hi), B=vt
    mma_gemm<2><<<dim3(2, 4, NB), blk, SMEM_BYTES>>>(
        wh + 5 * sW, C_CH, 0, vth, vtl, C_CH, sP,
        nullptr, valh, vall, KR, sP, s + 5 * C_CH, b + 5 * C_CH, C_CH);

    // sim[p,k] = sum_c q[p,c]*key[k,c]  (f32 logits)
    mma_gemm<4><<<dim3(2, 128, NB), blk, SMEM_BYTES>>>(
        qb, C_CH, sBig, keyh, keyl, C_CH, sP,
        simf, nullptr, nullptr, KR, sSim, nullptr, nullptr, C_CH);

    // softmax over k -> probs fp16
    softmax_h<<<(NB * HW_) / 8, 256>>>(simf, pr, 0.044194173824159216f, NB * HW_);

    // ctx[p,c] = sum_k probs[p,k]*val[c,k]  (hi-only out, no act)
    mma_gemm<3><<<dim3(4, 128, NB), blk, SMEM_BYTES>>>(
        pr, KR, sSim, valh, vall, KR, sP,
        nullptr, cx, nullptr, C_CH, sBig, nullptr, nullptr, KR);

    // f_up: out[c,p] = relu(s6*(sum_c' cx[p,c']*W6[c,c']) + b6), transposed f32
    mma_gemm<5><<<dim3(4, 128, NB), blk, SMEM_BYTES>>>(
        cx, C_CH, sBig, wh + 6 * sW, wl + 6 * sW, C_CH, 0,
        out, nullptr, nullptr, HW_, (long long)C_CH * HW_,
        s + 6 * C_CH, b + 6 * C_CH, C_CH);
}

// round 17
// speedup vs baseline: 5.5064x; 1.4609x over previous
#include <cuda_runtime.h>
#include <cuda_fp16.h>
#include <stdint.h>

#define C_CH 512
#define HW_  16384
#define NB   8
#define KR   256

typedef __half f16;

// ---------------------------------------------------------------------------
// Static device scratch (allocation-free rule) — everything single fp16
// ---------------------------------------------------------------------------
__device__ f16 g_x  [(size_t)NB * HW_ * C_CH];
__device__ f16 g_t0 [(size_t)NB * HW_ * C_CH];
__device__ f16 g_q  [(size_t)NB * HW_ * C_CH];
__device__ f16 g_cx [(size_t)NB * HW_ * C_CH];
__device__ float g_sim[(size_t)NB * HW_ * KR];
__device__ f16 g_pr [(size_t)NB * HW_ * KR];
__device__ f16 g_pb [(size_t)NB * KR * C_CH];
__device__ f16 g_kt [(size_t)NB * KR * C_CH];
__device__ f16 g_key[(size_t)NB * KR * C_CH];
__device__ f16 g_vt [(size_t)NB * KR * C_CH];
__device__ f16 g_val[(size_t)NB * C_CH * KR];
__device__ f16 g_w  [(size_t)7 * C_CH * C_CH];

// ---------------------------------------------------------------------------
// mma.sync / ldmatrix / cp.async helpers (legal on target sm_103, no 'a')
// ---------------------------------------------------------------------------
static __device__ __forceinline__ uint32_t smem_u32(const void* p) {
    uint32_t a;
    asm("{ .reg .u64 t; cvta.to.shared.u64 t, %1; cvt.u32.u64 %0, t; }"
        : "=r"(a) : "l"(p));
    return a;
}
static __device__ __forceinline__ void cpa16(uint32_t saddr, const void* g) {
    asm volatile("cp.async.cg.shared.global [%0], [%1], 16;"
                 :: "r"(saddr), "l"(g));
}
static __device__ __forceinline__ void cpa_commit() {
    asm volatile("cp.async.commit_group;" ::: "memory");
}
static __device__ __forceinline__ void cpa_wait0() {
    asm volatile("cp.async.wait_group 0;" ::: "memory");
}
static __device__ __forceinline__ void ldm4(uint32_t* d, uint32_t addr) {
    asm volatile("ldmatrix.sync.aligned.m8n8.x4.shared.b16 {%0,%1,%2,%3}, [%4];"
                 : "=r"(d[0]), "=r"(d[1]), "=r"(d[2]), "=r"(d[3]) : "r"(addr));
}
static __device__ __forceinline__ void mma16816(float* c, const uint32_t* a,
                                                uint32_t b0, uint32_t b1) {
    asm volatile(
        "mma.sync.aligned.m16n8k16.row.col.f32.f16.f16.f32 "
        "{%0,%1,%2,%3}, {%4,%5,%6,%7}, {%8,%9}, {%0,%1,%2,%3};"
        : "+f"(c[0]), "+f"(c[1]), "+f"(c[2]), "+f"(c[3])
        : "r"(a[0]), "r"(a[1]), "r"(a[2]), "r"(a[3]), "r"(b0), "r"(b1));
}

// 16B-granular XOR swizzle over rows of 64B (32 f16): conflict-free for the
// 4-seg row writes and for ldmatrix 8-row gathers.
static __device__ __forceinline__ uint32_t swz(int row, int kb) {
    return (uint32_t)(row * 64 + kb) ^ (uint32_t)((row & 7) << 4);
}

// SMEM: 2 stages x (A 8K | B 8K) = 32 KiB; EPI5 transpose needs 33792
#define STAGE_BYTES 16384
#define SMEM_MAIN   (2 * STAGE_BYTES)      // 32768
#define SMEM_EPI5   34048                  // >= 64*132*4 = 33792, 128-aligned

// ---------------------------------------------------------------------------
// Tensor-core GEMM:  O[m,n] = sum_k A[m,k]*B[n,k]   (pure fp16, f32 accum)
// EPI: 0 = hi out, relu, chan=n     2 = hi out, relu, chan=m
//      3 = hi out, no act           4 = f32 out [m][n]
//      5 = f32 out transposed [n][m] via SMEM (coalesced), relu, chan=n
// Block 128x128, BK=32, 256 thr (8 warps of 32x64), cp.async double buffer,
// single __syncthreads per K-chunk (R9/R16-proven skeleton).
// ---------------------------------------------------------------------------
template<int EPI>
__global__ void __launch_bounds__(256, 2) mma_gemm(
    const f16* __restrict__ A, int lda, long long sA,
    const f16* __restrict__ B, int ldb, long long sB,
    float* __restrict__ Of, f16* __restrict__ Oh,
    int ldo, long long sO,
    const float* __restrict__ scale, const float* __restrict__ bias, int Ktot)
{
    extern __shared__ __align__(128) char smem[];
    const uint32_t sb = smem_u32(smem);
    const int tid  = threadIdx.x;
    const int lane = tid & 31, w = tid >> 5;
    const int wm = (w >> 1) * 32, wn = (w & 1) * 64;
    const int n0 = blockIdx.x * 128, m0 = blockIdx.y * 128, z = blockIdx.z;

    const f16* pA = A + (size_t)z * sA + (size_t)m0 * lda;
    const f16* pB = B + (size_t)z * sB + (size_t)n0 * ldb;

    // ---- async stage loader: 4 x 16B cp.async per thread ----
    auto stage_load = [&](int st, int k0) {
        const uint32_t base = sb + st * STAGE_BYTES;
        #pragma unroll
        for (int it = 0; it < 2; ++it) {
            const int seg = tid + it * 256;          // 0..511
            const int row = seg >> 2;                // 0..127
            const int kb  = (seg & 3) << 4;          // byte offset in row
            const uint32_t so = swz(row, kb);
            const int ke = (kb >> 1);                // f16 elem offset
            cpa16(base + 0    + so, pA + (size_t)row * lda + k0 + ke);
            cpa16(base + 8192 + so, pB + (size_t)row * ldb + k0 + ke);
        }
        cpa_commit();
    };

    float acc[2][8][4];
    #pragma unroll
    for (int mt = 0; mt < 2; ++mt)
        #pragma unroll
        for (int nt = 0; nt < 8; ++nt)
            #pragma unroll
            for (int e = 0; e < 4; ++e) acc[mt][nt][e] = 0.f;

    const int q = lane >> 3, r = lane & 7;   // ldmatrix lane decomposition
    const int nch = Ktot >> 5;

    stage_load(0, 0);
    for (int c = 0; c < nch; ++c) {
        cpa_wait0();
        __syncthreads();
        if (c + 1 < nch) stage_load((c + 1) & 1, (c + 1) * 32);

        const uint32_t abase = sb + (c & 1) * STAGE_BYTES;
        const uint32_t bbase = abase + 8192;

        #pragma unroll
        for (int kk = 0; kk < 2; ++kk) {
            uint32_t ah[2][4];
            #pragma unroll
            for (int mt = 0; mt < 2; ++mt) {
                const int arow = wm + mt * 16 + ((q & 1) << 3) + r;
                const int kb   = kk * 32 + ((q >> 1) << 4);
                ldm4(ah[mt], abase + swz(arow, kb));
            }
            #pragma unroll
            for (int np = 0; np < 4; ++np) {
                const int brow = wn + np * 16 + ((q >> 1) << 3) + r;
                const int kb   = kk * 32 + ((q & 1) << 4);
                uint32_t bh[4];
                ldm4(bh, bbase + swz(brow, kb));
                #pragma unroll
                for (int s2 = 0; s2 < 2; ++s2) {
                    const int nt = np * 2 + s2;
                    #pragma unroll
                    for (int mt = 0; mt < 2; ++mt)
                        mma16816(acc[mt][nt], ah[mt], bh[2 * s2], bh[2 * s2 + 1]);
                }
            }
        }
    }

    // ---- epilogue ----
    if constexpr (EPI == 5) {
        // Two-pass transpose through SMEM, coalesced f32 stores.
        float* tb = (float*)smem;
        const int pad = 132;
        #pragma unroll
        for (int p = 0; p < 2; ++p) {
            __syncthreads();
            if ((w & 1) == p) {
                #pragma unroll
                for (int mt = 0; mt < 2; ++mt)
                    #pragma unroll
                    for (int nt = 0; nt < 8; ++nt) {
                        const float* cc = acc[mt][nt];
                        #pragma unroll
                        for (int h = 0; h < 2; ++h) {
                            const int ml = wm + mt * 16 + (lane >> 2) + h * 8;
                            const int nl = nt * 8 + (lane & 3) * 2;
                            const int n  = n0 + p * 64 + nl;
                            float v0 = fmaxf(fmaf(scale[n],     cc[h*2+0], bias[n]),     0.f);
                            float v1 = fmaxf(fmaf(scale[n + 1], cc[h*2+1], bias[n + 1]), 0.f);
                            tb[(size_t)nl * pad + ml]       = v0;
                            tb[(size_t)(nl + 1) * pad + ml] = v1;
                        }
                    }
            }
            __syncthreads();
            float* ob = Of + (size_t)z * sO + (size_t)(n0 + p * 64) * ldo + m0;
            #pragma unroll
            for (int i = 0; i < 8; ++i) {
                const int nrow = w * 8 + i;
                const float* src = tb + (size_t)nrow * pad + lane * 4;
                float4 v;
                v.x = src[0]; v.y = src[1]; v.z = src[2]; v.w = src[3];
                *(float4*)(ob + (size_t)nrow * ldo + lane * 4) = v;
            }
        }
        return;
    }

    #pragma unroll
    for (int mt = 0; mt < 2; ++mt) {
        #pragma unroll
        for (int nt = 0; nt < 8; ++nt) {
            const float* cc = acc[mt][nt];
            #pragma unroll
            for (int h = 0; h < 2; ++h) {
                const int m = m0 + wm + mt * 16 + (lane >> 2) + h * 8;
                const int n = n0 + wn + nt * 8 + (lane & 3) * 2;
                float v0 = cc[h * 2 + 0];
                float v1 = cc[h * 2 + 1];
                if constexpr (EPI == 0) {
                    v0 = fmaxf(fmaf(scale[n],     v0, bias[n]),     0.f);
                    v1 = fmaxf(fmaf(scale[n + 1], v1, bias[n + 1]), 0.f);
                } else if constexpr (EPI == 2) {
                    const float sm_ = scale[m], bm_ = bias[m];
                    v0 = fmaxf(fmaf(sm_, v0, bm_), 0.f);
                    v1 = fmaxf(fmaf(sm_, v1, bm_), 0.f);
                }
                if constexpr (EPI == 4) {
                    float2 v; v.x = v0; v.y = v1;
                    *(float2*)(Of + (size_t)z * sO + (size_t)m * ldo + n) = v;
                } else {
                    const size_t off = (size_t)z * sO + (size_t)m * ldo + n;
                    __half2 hh; hh.x = __float2half(v0); hh.y = __float2half(v1);
                    *(__half2*)(Oh + off) = hh;
                }
            }
        }
    }
}

// ---------------------------------------------------------------------------
// Conversion kernels
// ---------------------------------------------------------------------------
__global__ void convert_w(const float* __restrict__ in, f16* __restrict__ oh, int n)
{
    int i = blockIdx.x * 256 + threadIdx.x;
    if (i >= n) return;
    oh[i] = __float2half(in[i]);
}

// in: [z][Cc][P] f32  ->  out: [z][P][Cc] fp16
__global__ void transpose_half(const float* __restrict__ in, f16* __restrict__ oh,
                               int P, int Cc)
{
    __shared__ float t[32][33];
    int z = blockIdx.z;
    int p0 = blockIdx.x * 32, c0 = blockIdx.y * 32;
    const float* ib = in + (size_t)z * Cc * P;
    int tx = threadIdx.x, ty = threadIdx.y;
    #pragma unroll
    for (int i = 0; i < 32; i += 8)
        t[ty + i][tx] = ib[(size_t)(c0 + ty + i) * P + p0 + tx];
    __syncthreads();
    f16* ohb = oh + (size_t)z * P * Cc;
    #pragma unroll
    for (int i = 0; i < 32; i += 8)
        ohb[(size_t)(p0 + ty + i) * Cc + c0 + tx] = __float2half(t[tx][ty + i]);
}

// softmax over K=256 per row; outputs fp16 probabilities
__global__ void softmax_h(const float* __restrict__ sim, f16* __restrict__ pr,
                          float scale, int nrows)
{
    const int warp = (int)((blockIdx.x * (unsigned)blockDim.x + threadIdx.x) >> 5);
    const int lane = threadIdx.x & 31;
    if (warp >= nrows) return;
    const float* row = sim + (size_t)warp * 256;

    float4 v0 = *(const float4*)(row + lane * 4);
    float4 v1 = *(const float4*)(row + 128 + lane * 4);

    float m = fmaxf(fmaxf(fmaxf(v0.x, v0.y), fmaxf(v0.z, v0.w)),
                    fmaxf(fmaxf(v1.x, v1.y), fmaxf(v1.z, v1.w)));
    #pragma unroll
    for (int o = 16; o; o >>= 1) m = fmaxf(m, __shfl_xor_sync(0xffffffffu, m, o));

    v0.x = __expf((v0.x - m) * scale); v0.y = __expf((v0.y - m) * scale);
    v0.z = __expf((v0.z - m) * scale); v0.w = __expf((v0.w - m) * scale);
    v1.x = __expf((v1.x - m) * scale); v1.y = __expf((v1.y - m) * scale);
    v1.z = __expf((v1.z - m) * scale); v1.w = __expf((v1.w - m) * scale);

    float s = v0.x + v0.y + v0.z + v0.w + v1.x + v1.y + v1.z + v1.w;
    #pragma unroll
    for (int o = 16; o; o >>= 1) s += __shfl_xor_sync(0xffffffffu, s, o);
    const float inv = 1.0f / s;

    f16* op = pr + (size_t)warp * 256;
    __half2 a0; a0.x = __float2half(v0.x * inv); a0.y = __float2half(v0.y * inv);
    __half2 a1; a1.x = __float2half(v0.z * inv); a1.y = __float2half(v0.w * inv);
    __half2 a2; a2.x = __float2half(v1.x * inv); a2.y = __float2half(v1.y * inv);
    __half2 a3; a3.x = __float2half(v1.z * inv); a3.y = __float2half(v1.w * inv);
    *(__half2*)(op + lane * 4)           = a0;
    *(__half2*)(op + lane * 4 + 2)       = a1;
    *(__half2*)(op + 128 + lane * 4)     = a2;
    *(__half2*)(op + 128 + lane * 4 + 2) = a3;
}

// ---------------------------------------------------------------------------
// kernel_launch
// Inputs: x [8,512,128,128], proxy [8,512,256,1], W [7,512,512], s [7,512], b [7,512]
// ---------------------------------------------------------------------------
extern "C" void kernel_launch(void* const* d_in, const int* in_sizes, int n_in,
                              void* d_out, int out_size)
{
    (void)in_sizes; (void)n_in; (void)out_size;
    const float* x     = (const float*)d_in[0];
    const float* proxy = (const float*)d_in[1];
    const float* W     = (const float*)d_in[2];
    const float* s     = (const float*)d_in[3];
    const float* b     = (const float*)d_in[4];
    float* out = (float*)d_out;

    f16 *xb,*t0,*qb,*cx,*pr,*pb,*kt,*key,*vt,*val,*wb;
    float *simf;
    cudaGetSymbolAddress((void**)&xb,  g_x);   cudaGetSymbolAddress((void**)&t0,  g_t0);
    cudaGetSymbolAddress((void**)&qb,  g_q);   cudaGetSymbolAddress((void**)&cx,  g_cx);
    cudaGetSymbolAddress((void**)&pr,  g_pr);  cudaGetSymbolAddress((void**)&pb,  g_pb);
    cudaGetSymbolAddress((void**)&kt,  g_kt);  cudaGetSymbolAddress((void**)&key, g_key);
    cudaGetSymbolAddress((void**)&vt,  g_vt);  cudaGetSymbolAddress((void**)&val, g_val);
    cudaGetSymbolAddress((void**)&wb,  g_w);   cudaGetSymbolAddress((void**)&simf,g_sim);

    cudaFuncSetAttribute(mma_gemm<0>, cudaFuncAttributeMaxDynamicSharedMemorySize, SMEM_MAIN);
    cudaFuncSetAttribute(mma_gemm<2>, cudaFuncAttributeMaxDynamicSharedMemorySize, SMEM_MAIN);
    cudaFuncSetAttribute(mma_gemm<3>, cudaFuncAttributeMaxDynamicSharedMemorySize, SMEM_MAIN);
    cudaFuncSetAttribute(mma_gemm<4>, cudaFuncAttributeMaxDynamicSharedMemorySize, SMEM_MAIN);
    cudaFuncSetAttribute(mma_gemm<5>, cudaFuncAttributeMaxDynamicSharedMemorySize, SMEM_EPI5);

    const long long sBig = (long long)HW_ * C_CH;     // 8388608
    const long long sP   = (long long)KR  * C_CH;     // 131072
    const long long sSim = (long long)HW_ * KR;       // 4194304
    const long long sW   = (long long)C_CH * C_CH;    // 262144

    // --- conversions ---
    convert_w<<<(int)((7 * sW + 255) / 256), 256>>>(W, wb, (int)(7 * sW));
    transpose_half<<<dim3(HW_ / 32, C_CH / 32, NB), dim3(32, 8)>>>(x, xb, HW_, C_CH);
    transpose_half<<<dim3(KR  / 32, C_CH / 32, NB), dim3(32, 8)>>>(proxy, pb, KR, C_CH);

    const dim3 blk(256);
    // f_pixel: x -> t0 -> q   (activations [p][c], chan on N)
    mma_gemm<0><<<dim3(4, 128, NB), blk, SMEM_MAIN>>>(
        xb, C_CH, sBig, wb + 0 * sW, C_CH, 0,
        nullptr, t0, C_CH, sBig, s + 0 * C_CH, b + 0 * C_CH, C_CH);
    mma_gemm<0><<<dim3(4, 128, NB), blk, SMEM_MAIN>>>(
        t0, C_CH, sBig, wb + 1 * sW, C_CH, 0,
        nullptr, qb, C_CH, sBig, s + 1 * C_CH, b + 1 * C_CH, C_CH);

    // f_object: proxy -> kt -> key   ([r][c])
    mma_gemm<0><<<dim3(4, 2, NB), blk, SMEM_MAIN>>>(
        pb, C_CH, sP, wb + 2 * sW, C_CH, 0,
        nullptr, kt, C_CH, sP, s + 2 * C_CH, b + 2 * C_CH, C_CH);
    mma_gemm<0><<<dim3(4, 2, NB), blk, SMEM_MAIN>>>(
        kt, C_CH, sP, wb + 3 * sW, C_CH, 0,
        nullptr, key, C_CH, sP, s + 3 * C_CH, b + 3 * C_CH, C_CH);

    // f_down: proxy -> vt ([r][c]) -> val ([c][r], chan on M)
    mma_gemm<0><<<dim3(4, 2, NB), blk, SMEM_MAIN>>>(
        pb, C_CH, sP, wb + 4 * sW, C_CH, 0,
        nullptr, vt, C_CH, sP, s + 4 * C_CH, b + 4 * C_CH, C_CH);
    mma_gemm<2><<<dim3(2, 4, NB), blk, SMEM_MAIN>>>(
        wb + 5 * sW, C_CH, 0, vt, C_CH, sP,
        nullptr, val, KR, sP, s + 5 * C_CH, b + 5 * C_CH, C_CH);

    // sim[p,k] = sum_c q[p,c]*key[k,c]  (f32 logits)
    mma_gemm<4><<<dim3(2, 128, NB), blk, SMEM_MAIN>>>(
        qb, C_CH, sBig, key, C_CH, sP,
        simf, nullptr, KR, sSim, nullptr, nullptr, C_CH);

    // softmax over k -> probs fp16
    softmax_h<<<(NB * HW_) / 8, 256>>>(simf, pr, 0.044194173824159216f, NB * HW_);

    // ctx[p,c] = sum_k probs[p,k]*val[c,k]  (no act)
    mma_gemm<3><<<dim3(4, 128, NB), blk, SMEM_MAIN>>>(
        pr, KR, sSim, val, KR, sP,
        nullptr, cx, C_CH, sBig, nullptr, nullptr, KR);

    // f_up: out[c,p] = relu(s6*(sum_c' cx[p,c']*W6[c,c']) + b6), transposed f32
    mma_gemm<5><<<dim3(4, 128, NB), blk, SMEM_EPI5>>>(
        cx, C_CH, sBig, wb + 6 * sW, C_CH, 0,
        out, nullptr, HW_, (long long)C_CH * HW_,
        s + 6 * C_CH, b + 6 * C_CH, C_CH);
}